// round 3
// baseline (speedup 1.0000x reference)
#include <cuda_runtime.h>
#include <math_constants.h>

// Problem constants (fixed by the reference: x=(128,128,16,16) f32, logits=(128,100))
#define B_  128
#define D_  32768          // C*H*W
#define D4_ (D_/4)         // 8192 float4 per prototype row
#define K_  100
#define TILE_ 10           // 10x10 class tile in the broadcast kernel

// Scratch (allocation-free rule: __device__ globals)
__device__ int   g_items[B_];    // CSR items: batch indices grouped by class, ascending
__device__ int   g_off[K_ + 1];  // CSR offsets
__device__ float g_inv[K_];      // 1/count (0 if count==0)

// ---------------------------------------------------------------------------
// Kernel 1: argmax per batch row + deterministic CSR build.
// 1024 threads, 8 threads per row -> ~13 independent LDGs per thread, so the
// whole 51KB logits read is latency-hidden (MLP in the thousands), vs. the
// previous 4-warp version that waited on DRAM ~25 times.
// softmax is monotone -> argmax(probs) == argmax(logits). Tie-breaking is
// explicit: higher value wins; on equal value, lower index wins (jnp.argmax).
// CSR: counts via smem atomics (order-independent), offsets via serial smem
// prefix, placement via stable rank scan -> bitwise-deterministic.
// ---------------------------------------------------------------------------
__global__ __launch_bounds__(1024) void argmax_csr_kernel(
        const float* __restrict__ logits) {
    __shared__ int s_cls[B_];
    __shared__ int s_cnt[K_];
    __shared__ int s_off[K_ + 1];

    int tid = threadIdx.x;        // 0..1023
    int b   = tid >> 3;           // row 0..127
    int sub = tid & 7;            // 0..7 within row

    if (tid < K_) s_cnt[tid] = 0;

    // strided partial argmax over this row's logits
    const float* row = logits + (size_t)b * K_;
    float v  = row[sub];          // every sub has >=1 element (100 > 8)
    int   idx = sub;
    #pragma unroll
    for (int k = sub + 8; k < K_; k += 8) {
        float t = row[k];
        if (t > v) { v = t; idx = k; }   // ascending scan + strict > => lowest index kept
    }
    // reduce across the 8-thread group (width=8 confines the shuffle)
    #pragma unroll
    for (int off = 4; off > 0; off >>= 1) {
        float ov = __shfl_down_sync(0xffffffffu, v,   off, 8);
        int   oi = __shfl_down_sync(0xffffffffu, idx, off, 8);
        if (ov > v || (ov == v && oi < idx)) { v = ov; idx = oi; }
    }
    __syncthreads();              // counts zeroed before atomics
    if (sub == 0) {
        s_cls[b] = idx;
        atomicAdd(&s_cnt[idx], 1);
    }
    __syncthreads();

    // serial prefix over 100 smem ints (cheap)
    if (tid == 0) {
        int off = 0;
        #pragma unroll 4
        for (int k = 0; k < K_; k++) { s_off[k] = off; off += s_cnt[k]; }
        s_off[K_] = off;
    }
    __syncthreads();

    // deterministic rank within class (threads 0..127, one per row)
    if (tid < B_) {
        int myc = s_cls[tid];
        int rank = 0;
        #pragma unroll 8
        for (int bb = 0; bb < B_; bb++)
            rank += (bb < tid && s_cls[bb] == myc) ? 1 : 0;
        g_items[s_off[myc] + rank] = tid;
    }

    // publish offsets + inverse counts
    if (tid < K_) {
        g_off[tid] = s_off[tid];
        int c = s_cnt[tid];
        g_inv[tid] = (c > 0) ? (1.0f / (float)c) : 0.0f;
    }
    if (tid == 0) g_off[K_] = s_off[K_];
}

// ---------------------------------------------------------------------------
// Kernel 2: prototypes[k][d] = mean over assigned batches (via CSR).
// grid = (D4/256, K). Reads x exactly once overall (coalesced float4),
// deterministic fixed-order accumulation, writes 12.8 MB.
// ---------------------------------------------------------------------------
__global__ void proto_kernel(const float4* __restrict__ x4,
                             float4* __restrict__ proto4) {
    int d4 = blockIdx.x * blockDim.x + threadIdx.x;   // 0..D4-1
    int k  = blockIdx.y;

    float4 acc = make_float4(0.f, 0.f, 0.f, 0.f);
    int s = g_off[k];
    int e = g_off[k + 1];
    for (int t = s; t < e; t++) {
        int b = g_items[t];
        float4 v = x4[(size_t)b * D4_ + d4];
        acc.x += v.x; acc.y += v.y; acc.z += v.z; acc.w += v.w;
    }
    float inv = g_inv[k];  // count==0 -> acc==0 and inv==0 -> 0 (matches where())
    acc.x *= inv; acc.y *= inv; acc.z *= inv; acc.w *= inv;
    proto4[(size_t)k * D4_ + d4] = acc;
}

// ---------------------------------------------------------------------------
// Kernel 3: inter[i][j][d] = proto[j][d] - proto[i][d].
// 1.31 GB of writes -> DRAM-write bound (measured ~6.4 TB/s effective, ~80%
// of spec). 10x10 class tile per block: pj[10] held in registers, pi
// streamed; prototype reads (12.8 MB) stay resident in L2, so DRAM traffic
// is the write stream only. All stores coalesced STG.128.
// grid = (D4/256, 100 tiles), block = 256.
// ---------------------------------------------------------------------------
__global__ __launch_bounds__(256) void inter_kernel(
        const float4* __restrict__ proto4,
        float4* __restrict__ out4) {
    int d4   = blockIdx.x * 256 + threadIdx.x;     // 0..D4-1
    int tile = blockIdx.y;                         // 0..99
    int i0 = (tile / TILE_) * TILE_;
    int j0 = (tile % TILE_) * TILE_;

    float4 pj[TILE_];
    #pragma unroll
    for (int jj = 0; jj < TILE_; jj++)
        pj[jj] = proto4[(size_t)(j0 + jj) * D4_ + d4];

    #pragma unroll
    for (int ii = 0; ii < TILE_; ii++) {
        float4 pi = proto4[(size_t)(i0 + ii) * D4_ + d4];
        #pragma unroll
        for (int jj = 0; jj < TILE_; jj++) {
            float4 r;
            r.x = pj[jj].x - pi.x;
            r.y = pj[jj].y - pi.y;
            r.z = pj[jj].z - pi.z;
            r.w = pj[jj].w - pi.w;
            out4[(size_t)((i0 + ii) * K_ + (j0 + jj)) * D4_ + d4] = r;
        }
    }
}

// ---------------------------------------------------------------------------
// Launcher. Output layout: [prototypes (100*32768 f32) | inter (100*100*32768 f32)]
// ---------------------------------------------------------------------------
extern "C" void kernel_launch(void* const* d_in, const int* in_sizes, int n_in,
                              void* d_out, int out_size) {
    const float* x      = (const float*)d_in[0];   // (128,128,16,16) f32
    const float* logits = (const float*)d_in[1];   // (128,100) f32
    float* out = (float*)d_out;

    const float4* x4     = (const float4*)x;
    float4*       proto4 = (float4*)out;                       // first 819200 float4
    float4*       inter4 = (float4*)out + (size_t)K_ * D4_;    // rest

    argmax_csr_kernel<<<1, 1024>>>(logits);

    dim3 gp(D4_ / 256, K_);        // 32 x 100
    proto_kernel<<<gp, 256>>>(x4, proto4);

    dim3 gi(D4_ / 256, K_);        // 32 x 100 tiles (10x10 class tiles)
    inter_kernel<<<gi, 256>>>(proto4, inter4);
}

// round 4
// speedup vs baseline: 1.1604x; 1.1604x over previous
#include <cuda_runtime.h>

// Problem constants (fixed by the reference: x=(128,128,16,16) f32, logits=(128,100))
#define B_  128
#define D_  32768          // C*H*W
#define D4_ (D_/4)         // 8192 float4 per prototype row
#define K_  100
#define TILE_ 10           // 10x10 class tile in the fused broadcast kernel

// Scratch (allocation-free rule: __device__ globals)
__device__ int   g_items[B_];    // CSR items: batch indices grouped by class, ascending
__device__ int   g_off[K_ + 1];  // CSR offsets
__device__ float g_inv[K_];      // 1/count (0 if count==0)

// ---------------------------------------------------------------------------
// Kernel 1: argmax per batch row + deterministic CSR build.
// 1024 threads, 8 threads per row -> ~13 independent LDGs per thread (high
// MLP). softmax is monotone -> argmax(probs) == argmax(logits); strict > with
// ascending scan + (value,index) shuffle reduce matches jnp.argmax ties.
// CSR: counts via smem atomics (order-independent), serial smem prefix,
// stable rank scan -> bitwise-deterministic.
// ---------------------------------------------------------------------------
__global__ __launch_bounds__(1024) void argmax_csr_kernel(
        const float* __restrict__ logits) {
    __shared__ int s_cls[B_];
    __shared__ int s_cnt[K_];
    __shared__ int s_off[K_ + 1];

    int tid = threadIdx.x;        // 0..1023
    int b   = tid >> 3;           // row 0..127
    int sub = tid & 7;            // 0..7 within row

    if (tid < K_) s_cnt[tid] = 0;

    const float* row = logits + (size_t)b * K_;
    float v   = row[sub];
    int   idx = sub;
    #pragma unroll
    for (int k = sub + 8; k < K_; k += 8) {
        float t = row[k];
        if (t > v) { v = t; idx = k; }   // ascending + strict > => lowest index kept
    }
    #pragma unroll
    for (int off = 4; off > 0; off >>= 1) {
        float ov = __shfl_down_sync(0xffffffffu, v,   off, 8);
        int   oi = __shfl_down_sync(0xffffffffu, idx, off, 8);
        if (ov > v || (ov == v && oi < idx)) { v = ov; idx = oi; }
    }
    __syncthreads();              // counts zeroed before atomics
    if (sub == 0) {
        s_cls[b] = idx;
        atomicAdd(&s_cnt[idx], 1);
    }
    __syncthreads();

    if (tid == 0) {
        int off = 0;
        #pragma unroll 4
        for (int k = 0; k < K_; k++) { s_off[k] = off; off += s_cnt[k]; }
        s_off[K_] = off;
    }
    __syncthreads();

    if (tid < B_) {
        int myc = s_cls[tid];
        int rank = 0;
        #pragma unroll 8
        for (int bb = 0; bb < B_; bb++)
            rank += (bb < tid && s_cls[bb] == myc) ? 1 : 0;
        g_items[s_off[myc] + rank] = tid;
    }

    if (tid < K_) {
        g_off[tid] = s_off[tid];
        int c = s_cnt[tid];
        g_inv[tid] = (c > 0) ? (1.0f / (float)c) : 0.0f;
    }
    if (tid == 0) g_off[K_] = s_off[K_];
}

// ---------------------------------------------------------------------------
// Fused kernel: prototypes + inter-class matrix.
// grid = (D4/256, 100 tiles of 10x10 classes), block = 256.
// Each block recomputes its 20 prototype rows directly from x (CSR cached in
// smem; accumulation in CSR order => bitwise-identical to a separate proto
// kernel). x (16 MB) is L2-resident after the first wave, so the extra proto
// recompute costs only ~335 MB of L2 reads against the 1.31 GB write stream.
// Diagonal tiles (i0==j0) also write the prototype output.
// All output stores use __stcs (evict-first): the 1.31 GB stream is never
// re-read, so don't let it thrash x/CSR out of L2.
// ---------------------------------------------------------------------------
__global__ __launch_bounds__(256) void inter_fused_kernel(
        const float4* __restrict__ x4,
        float4* __restrict__ proto4,
        float4* __restrict__ out4) {
    __shared__ int   s_off[K_ + 1];
    __shared__ int   s_items[B_];
    __shared__ float s_inv[K_];

    int t = threadIdx.x;
    if (t < K_ + 1) s_off[t]   = g_off[t];
    if (t < B_)     s_items[t] = g_items[t];
    if (t < K_)     s_inv[t]   = g_inv[t];
    __syncthreads();

    int d4   = blockIdx.x * 256 + t;               // 0..D4-1
    int tile = blockIdx.y;                         // 0..99
    int i0 = (tile / TILE_) * TILE_;
    int j0 = (tile % TILE_) * TILE_;
    bool diag = (i0 == j0);

    // prototype rows j0..j0+9 (kept in registers for the whole tile)
    float4 pj[TILE_];
    #pragma unroll
    for (int jj = 0; jj < TILE_; jj++) {
        int k = j0 + jj;
        float4 acc = make_float4(0.f, 0.f, 0.f, 0.f);
        int s = s_off[k], e = s_off[k + 1];
        for (int u = s; u < e; u++) {
            float4 v = x4[(size_t)s_items[u] * D4_ + d4];
            acc.x += v.x; acc.y += v.y; acc.z += v.z; acc.w += v.w;
        }
        float inv = s_inv[k];    // count==0 -> acc==0, inv==0 -> 0 (matches where())
        acc.x *= inv; acc.y *= inv; acc.z *= inv; acc.w *= inv;
        pj[jj] = acc;
    }

    // diagonal tiles publish the prototype output (covers all 100 classes)
    if (diag) {
        #pragma unroll
        for (int jj = 0; jj < TILE_; jj++)
            __stcs(&proto4[(size_t)(j0 + jj) * D4_ + d4], pj[jj]);
    }

    #pragma unroll
    for (int ii = 0; ii < TILE_; ii++) {
        int k = i0 + ii;
        float4 pi;
        if (diag) {
            pi = pj[ii];
        } else {
            float4 acc = make_float4(0.f, 0.f, 0.f, 0.f);
            int s = s_off[k], e = s_off[k + 1];
            for (int u = s; u < e; u++) {
                float4 v = x4[(size_t)s_items[u] * D4_ + d4];
                acc.x += v.x; acc.y += v.y; acc.z += v.z; acc.w += v.w;
            }
            float inv = s_inv[k];
            acc.x *= inv; acc.y *= inv; acc.z *= inv; acc.w *= inv;
            pi = acc;
        }
        #pragma unroll
        for (int jj = 0; jj < TILE_; jj++) {
            float4 r;
            r.x = pj[jj].x - pi.x;
            r.y = pj[jj].y - pi.y;
            r.z = pj[jj].z - pi.z;
            r.w = pj[jj].w - pi.w;
            __stcs(&out4[(size_t)((i0 + ii) * K_ + (j0 + jj)) * D4_ + d4], r);
        }
    }
}

// ---------------------------------------------------------------------------
// Launcher. Output layout: [prototypes (100*32768 f32) | inter (100*100*32768 f32)]
// ---------------------------------------------------------------------------
extern "C" void kernel_launch(void* const* d_in, const int* in_sizes, int n_in,
                              void* d_out, int out_size) {
    const float* x      = (const float*)d_in[0];   // (128,128,16,16) f32
    const float* logits = (const float*)d_in[1];   // (128,100) f32
    float* out = (float*)d_out;

    const float4* x4     = (const float4*)x;
    float4*       proto4 = (float4*)out;                       // first 819200 float4
    float4*       inter4 = (float4*)out + (size_t)K_ * D4_;    // rest

    argmax_csr_kernel<<<1, 1024>>>(logits);

    dim3 gi(D4_ / 256, K_);        // 32 x 100 tiles (10x10 class tiles)
    inter_fused_kernel<<<gi, 256>>>(x4, proto4, inter4);
}